// round 14
// baseline (speedup 1.0000x reference)
#include <cuda_runtime.h>
#include <math.h>

#define NN 10000
#define NE 160000
#define FD 128
#define NBASIS 8
#define NHID 64
#define NSPEC 10
#define NCHK2 (NE/128)               // 1250 chunks of 128 edges
#define GRIDE2 304                   // 152 SMs x 2 blocks
#define PERM_SZ (NN + 16*NSPEC)
#define RMAXF 5.0f
#define PI_F 3.14159265358979323846f

// k_edge dynamic smem layout (floats):
// W2c[8192] | h0[8448] | h1[8448] | W1s[512] | b1s[64] | idx[512 ints]
#define SM_H0   8192
#define SM_H1   16640
#define SM_W1   25088
#define SM_B1   25600
#define SM_IDX  25664
#define SMEM_EDGE (25664*4 + 512*4)   // 104704 bytes

typedef unsigned long long ull;

// ---------------- device scratch (static, no allocations) ----------------
__device__ __align__(16) float g_rb[NE*NBASIS];     // radial basis per edge [E][8]
__device__ __align__(16) float g_scal[NN*FD];       // node scalar features
__device__ __align__(16) float g_agg[NN*FD];        // aggregated messages
__device__ __align__(16) float g_w2t[2*NHID*FD];    // W2 l=0 cols, transposed [layer][j][ch]
__device__ int   g_cnt[NSPEC];       // zero at module load; re-zeroed by k_node<true>
__device__ int   g_cur[NSPEC];
__device__ int   g_off[NSPEC+1];
__device__ int   g_perm[PERM_SZ];

// ---------------- f32x2 / vector-red helpers --------------------------------
__device__ __forceinline__ ull dup2(float w){
    ull r; asm("mov.b64 %0, {%1, %1};" : "=l"(r) : "f"(w)); return r;
}
__device__ __forceinline__ ull pack2(float a, float b){
    ull r; asm("mov.b64 %0, {%1, %2};" : "=l"(r) : "f"(a), "f"(b)); return r;
}
__device__ __forceinline__ void ffma2(ull& acc, ull a, ull b){
    asm("fma.rn.f32x2 %0, %1, %2, %0;" : "+l"(acc) : "l"(a), "l"(b));
}
__device__ __forceinline__ float2 unpk(ull v){
    float2 r; asm("mov.b64 {%0, %1}, %2;" : "=f"(r.x), "=f"(r.y) : "l"(v)); return r;
}
__device__ __forceinline__ void red4(float* p, float a, float b, float c, float d){
    asm volatile("red.global.add.v4.f32 [%0], {%1,%2,%3,%4};"
                 :: "l"(p), "f"(a), "f"(b), "f"(c), "f"(d) : "memory");
}

// ---------------- k_prep: w2t + perm init | geom | scal/agg init + counts ---
// blocks [0,64): W2 transpose, perm=-1
// blocks [64,689): radial basis (625 blocks)
// blocks [689,1939): scal=emb[spec], agg=0, species counting (cnt pre-zeroed)
__global__ void k_prep(const float* __restrict__ vec, const float* __restrict__ W2,
                       const int* __restrict__ spec, const float* __restrict__ emb){
    int b = blockIdx.x;
    if (b < 64){
        int idx = b*256 + threadIdx.x;
        if (idx < 2*NHID*FD){
            int l = idx >> 13, rem = idx & 8191;
            int j = rem >> 7, ch = rem & 127;
            g_w2t[idx] = W2[l*NHID*FD*4 + j*FD*4 + ch*4];
        }
        if (idx < PERM_SZ) g_perm[idx] = -1;
    } else if (b < 689){
        int e = (b - 64)*256 + threadIdx.x;
        float x = vec[3*e+0], y = vec[3*e+1], z = vec[3*e+2];
        float r = sqrtf(x*x + y*y + z*z);
        r = fmaxf(r, 1e-9f);
        float rc  = fminf(r, RMAXF);
        float cut = 0.5f*(__cosf(PI_F*rc/RMAXF) + 1.0f);
        float pref = sqrtf(2.0f/RMAXF) / r * cut;
        float arg = PI_F * r / RMAXF;
        float s1 = __sinf(arg), c2 = 2.0f*__cosf(arg);
        float v[NBASIS];
        float sm1 = 0.0f, s = s1;
        #pragma unroll
        for (int n = 0; n < NBASIS; n++){
            v[n] = pref * s;
            float sn = c2*s - sm1;
            sm1 = s; s = sn;
        }
        float4* dst = (float4*)&g_rb[(size_t)e*NBASIS];
        dst[0] = make_float4(v[0], v[1], v[2], v[3]);
        dst[1] = make_float4(v[4], v[5], v[6], v[7]);
    } else {
        int idx = (b - 689)*256 + threadIdx.x;
        int n = idx >> 5, f4 = idx & 31;
        int s = spec[n];
        ((float4*)g_scal)[idx] = ((const float4*)emb)[s*32 + f4];
        ((float4*)g_agg)[idx]  = make_float4(0.f, 0.f, 0.f, 0.f);
        if (f4 == 0) atomicAdd(&g_cnt[s], 1);
    }
}

// ---------------- merged offsets + placement ---------------------------------
__global__ void k_b24(const int* __restrict__ spec){
    __shared__ int offs[NSPEC];
    if (threadIdx.x == 0){
        int o = 0;
        #pragma unroll
        for (int s = 0; s < NSPEC; s++){ offs[s] = o; o += (g_cnt[s] + 15) & ~15; }
        if (blockIdx.x == 0){
            #pragma unroll
            for (int s = 0; s < NSPEC; s++) g_off[s] = offs[s];
            g_off[NSPEC] = o;
        }
    }
    __syncthreads();
    int n = blockIdx.x*256 + threadIdx.x;
    if (n < NN){
        int s = spec[n];
        int p = atomicAdd(&g_cur[s], 1);
        g_perm[offs[s] + p] = n;
    }
}

// ---------------- fused edge kernel (pipelined, 1 barrier/chunk) -------------
// 304 blocks x 256 threads; 8 warps = (4 edge-quarters of 32e) x (2 ch-halves).
// Double-buffered h_t: each warp computes h(c+G) for its own 32 edges (rb in
// regs, prefetched a full chunk ahead), then GEMM(c) from the other buffer.
__global__ __launch_bounds__(256, 2) void k_edge(
    const float* __restrict__ W1, const float* __restrict__ b1,
    const float* __restrict__ W2t,
    const int* __restrict__ snd, const int* __restrict__ rcv)
{
    extern __shared__ float sm[];
    float* W2c = sm;
    float* W1s = sm + SM_W1;
    float* b1s = sm + SM_B1;
    int*   ib  = (int*)(sm + SM_IDX);   // [buf][snd 0..128 | rcv 128..256]
    int tid = threadIdx.x, lane = tid & 31, w = tid >> 5;

    {   // stage weights once per block
        const float4* src = (const float4*)W2t;
        float4* dst = (float4*)W2c;
        #pragma unroll
        for (int i = 0; i < 8; i++) dst[tid + i*256] = src[tid + i*256];
    }
    for (int i = tid; i < NBASIS*NHID; i += 256) W1s[i] = W1[i];
    if (tid < NHID) b1s[tid] = b1[tid];
    __syncthreads();                     // W1s/b1s ready for prologue h

    int eq = w & 3, chalf = w >> 2;
    int cg = lane >> 2, eg = lane & 3;
    int ch0 = chalf*64 + cg*4;
    int eb0 = eq*32 + eg*8;              // GEMM: lane's first edge in chunk
    int ehw = eq*32 + lane;              // h-phase: lane's edge in chunk
    int jb  = chalf*32;                  // h-phase: j range base (0 or 32)

    // ---- prologue: h(ck) + idx(ck) -> buffer 0; prefetch ck+G ----
    int ck = blockIdx.x;
    {
        const float4* rp = (const float4*)&g_rb[(size_t)(ck*128 + ehw)*NBASIS];
        float4 ra = __ldg(rp), rb4 = __ldg(rp + 1);
        float rbv[NBASIS] = {ra.x, ra.y, ra.z, ra.w, rb4.x, rb4.y, rb4.z, rb4.w};
        float* hbuf = sm + SM_H0;
        #pragma unroll 4
        for (int q = 0; q < 32; q++){
            int j = jb + q;
            float a = b1s[j];
            #pragma unroll
            for (int k = 0; k < NBASIS; k++)
                a = fmaf(rbv[k], W1s[k*NHID + j], a);
            hbuf[j*132 + ehw] = __fdividef(a, 1.0f + __expf(-a));
        }
        int e0 = ck*128;
        ib[tid] = (tid < 128) ? snd[e0 + tid] : rcv[e0 + tid - 128];
    }
    float4 pra, prb; int pidx = 0;
    {
        int ck1 = ck + GRIDE2;
        if (ck1 < NCHK2){
            const float4* rp = (const float4*)&g_rb[(size_t)(ck1*128 + ehw)*NBASIS];
            pra = __ldg(rp); prb = __ldg(rp + 1);
            pidx = (tid < 128) ? snd[ck1*128 + tid] : rcv[ck1*128 + tid - 128];
        }
    }
    __syncthreads();                     // buffer 0 ready
    int par = 0;

    while (ck < NCHK2){
        int ckn = ck + GRIDE2;
        // ---- step 1: h(ckn) + idx(ckn) -> other buffer (from prefetch regs) --
        if (ckn < NCHK2){
            float rbv[NBASIS] = {pra.x, pra.y, pra.z, pra.w, prb.x, prb.y, prb.z, prb.w};
            float* hbuf = sm + (par ? SM_H0 : SM_H1);
            #pragma unroll 4
            for (int q = 0; q < 32; q++){
                int j = jb + q;
                float a = b1s[j];
                #pragma unroll
                for (int k = 0; k < NBASIS; k++)
                    a = fmaf(rbv[k], W1s[k*NHID + j], a);
                hbuf[j*132 + ehw] = __fdividef(a, 1.0f + __expf(-a));
            }
            ib[(par^1)*256 + tid] = pidx;
        }
        // ---- step 2: prefetch chunk ckn+G (consumed next iteration) ----
        int ck2 = ckn + GRIDE2;
        if (ck2 < NCHK2){
            const float4* rp = (const float4*)&g_rb[(size_t)(ck2*128 + ehw)*NBASIS];
            pra = __ldg(rp); prb = __ldg(rp + 1);
            pidx = (tid < 128) ? snd[ck2*128 + tid] : rcv[ck2*128 + tid - 128];
        }

        // ---- step 3: GEMM(ck) : 32e x 64ch register tile from h_t[par] ----
        const float* hb = sm + (par ? SM_H1 : SM_H0);
        ull acc[8][4];
        #pragma unroll
        for (int c = 0; c < 8; c++)
            #pragma unroll
            for (int p = 0; p < 4; p++) acc[c][p] = 0ULL;

        #pragma unroll 2
        for (int j = 0; j < NHID; j++){
            float4 wa = *(const float4*)&W2c[j*FD + ch0];
            float4 wb = *(const float4*)&W2c[j*FD + ch0 + 32];
            ulonglong2 ha = *(const ulonglong2*)&hb[j*132 + eb0];
            ulonglong2 hbv = *(const ulonglong2*)&hb[j*132 + eb0 + 4];
            ull wd0 = dup2(wa.x), wd1 = dup2(wa.y), wd2 = dup2(wa.z), wd3 = dup2(wa.w);
            ull wd4 = dup2(wb.x), wd5 = dup2(wb.y), wd6 = dup2(wb.z), wd7 = dup2(wb.w);
            ffma2(acc[0][0], ha.x, wd0); ffma2(acc[0][1], ha.y, wd0);
            ffma2(acc[0][2], hbv.x, wd0); ffma2(acc[0][3], hbv.y, wd0);
            ffma2(acc[1][0], ha.x, wd1); ffma2(acc[1][1], ha.y, wd1);
            ffma2(acc[1][2], hbv.x, wd1); ffma2(acc[1][3], hbv.y, wd1);
            ffma2(acc[2][0], ha.x, wd2); ffma2(acc[2][1], ha.y, wd2);
            ffma2(acc[2][2], hbv.x, wd2); ffma2(acc[2][3], hbv.y, wd2);
            ffma2(acc[3][0], ha.x, wd3); ffma2(acc[3][1], ha.y, wd3);
            ffma2(acc[3][2], hbv.x, wd3); ffma2(acc[3][3], hbv.y, wd3);
            ffma2(acc[4][0], ha.x, wd4); ffma2(acc[4][1], ha.y, wd4);
            ffma2(acc[4][2], hbv.x, wd4); ffma2(acc[4][3], hbv.y, wd4);
            ffma2(acc[5][0], ha.x, wd5); ffma2(acc[5][1], ha.y, wd5);
            ffma2(acc[5][2], hbv.x, wd5); ffma2(acc[5][3], hbv.y, wd5);
            ffma2(acc[6][0], ha.x, wd6); ffma2(acc[6][1], ha.y, wd6);
            ffma2(acc[6][2], hbv.x, wd6); ffma2(acc[6][3], hbv.y, wd6);
            ffma2(acc[7][0], ha.x, wd7); ffma2(acc[7][1], ha.y, wd7);
            ffma2(acc[7][2], hbv.x, wd7); ffma2(acc[7][3], hbv.y, wd7);
        }

        // ---- step 4: unpack + scatter (idx from buffer par) ----
        const int* sndp = ib + par*256;
        const int* rcvp = ib + par*256 + 128;
        #pragma unroll
        for (int p = 0; p < 4; p++){
            float2 m0 = unpk(acc[0][p]), m1 = unpk(acc[1][p]);
            float2 m2 = unpk(acc[2][p]), m3 = unpk(acc[3][p]);
            float2 m4 = unpk(acc[4][p]), m5 = unpk(acc[5][p]);
            float2 m6 = unpk(acc[6][p]), m7 = unpk(acc[7][p]);
            int ea = eb0 + 2*p, eb = ea + 1;
            {
                int sidx = sndp[ea], ridx = rcvp[ea];
                float4 ssa = *(const float4*)&g_scal[sidx*FD + ch0];
                float4 ssb = *(const float4*)&g_scal[sidx*FD + ch0 + 32];
                red4(&g_agg[ridx*FD + ch0],
                     m0.x*ssa.x, m1.x*ssa.y, m2.x*ssa.z, m3.x*ssa.w);
                red4(&g_agg[ridx*FD + ch0 + 32],
                     m4.x*ssb.x, m5.x*ssb.y, m6.x*ssb.z, m7.x*ssb.w);
            }
            {
                int sidx = sndp[eb], ridx = rcvp[eb];
                float4 ssa = *(const float4*)&g_scal[sidx*FD + ch0];
                float4 ssb = *(const float4*)&g_scal[sidx*FD + ch0 + 32];
                red4(&g_agg[ridx*FD + ch0],
                     m0.y*ssa.x, m1.y*ssa.y, m2.y*ssa.z, m3.y*ssa.w);
                red4(&g_agg[ridx*FD + ch0 + 32],
                     m4.y*ssb.x, m5.y*ssb.y, m6.y*ssb.z, m7.y*ssb.w);
            }
        }
        __syncthreads();                 // buffers swap safely
        ck = ckn; par ^= 1;
    }
}

// ---------------- fused node kernel + readout (f32x2-packed GEMV) ------------
template<bool HAS_SC>
__global__ __launch_bounds__(128) void k_node(
    const float* __restrict__ linW,
    const float* __restrict__ scWp,
    const float* __restrict__ pc,
    const float* __restrict__ roA,      // ro0W (L0) / ro1W1 (L1)
    const float* __restrict__ roB,      // unused (L0) / ro1W2 (L1)
    float* __restrict__ out)
{
    int tid = threadIdx.x;
    int c16 = blockIdx.x * 16;
    if (c16 >= g_off[NSPEC]) return;
    int s = 0;
    while (c16 >= g_off[s+1]) s++;

    __shared__ int   nodes[16];
    __shared__ float Wl[16*FD];
    __shared__ float Ws[16*FD];
    __shared__ float Aa[16*16];
    __shared__ float As[16*16];
    if (tid < 16) nodes[tid] = g_perm[c16 + tid];

    ull aU[8], aV[8];
    #pragma unroll
    for (int rp = 0; rp < 8; rp++){ aU[rp] = 0ULL; aV[rp] = 0ULL; }

    const float* WL = linW + (size_t)s * 4 * FD * FD;
    const float* WS = HAS_SC ? (scWp + (size_t)s * 4 * FD * FD) : linW;

    for (int ft0 = 0; ft0 < FD; ft0 += 16){
        __syncthreads();
        for (int i = tid; i < 16*FD; i += 128){
            int r = i >> 7, gg = i & 127;
            Wl[i] = WL[(ft0 + r)*FD + gg];
            if (HAS_SC) Ws[i] = WS[(ft0 + r)*FD + gg];
        }
        for (int i = tid; i < 256; i += 128){
            int r = i >> 4, nd = nodes[r];
            int fc = ft0 + (i & 15);
            Aa[i] = (nd < 0) ? 0.0f : g_agg[nd*FD + fc];
            if (HAS_SC) As[i] = (nd < 0) ? 0.0f : g_scal[nd*FD + fc];
        }
        __syncthreads();
        for (int ft = 0; ft < 16; ft++){
            ull wld = dup2(Wl[ft*FD + tid]);
            ull wsd = HAS_SC ? dup2(Ws[ft*FD + tid]) : 0ULL;
            #pragma unroll
            for (int rp = 0; rp < 8; rp++){
                ull a2 = pack2(Aa[(2*rp)*16 + ft], Aa[(2*rp+1)*16 + ft]);
                ffma2(aU[rp], a2, wld);
                if (HAS_SC){
                    ull s2 = pack2(As[(2*rp)*16 + ft], As[(2*rp+1)*16 + ft]);
                    ffma2(aV[rp], s2, wsd);
                }
            }
        }
    }
    const float* C = pc + s*3*FD;
    float c0 = C[tid], c1 = C[FD + tid], c2 = C[2*FD + tid];
    float ov[16];
    #pragma unroll
    for (int rp = 0; rp < 8; rp++){
        float2 u = unpk(aU[rp]);
        float2 v = HAS_SC ? unpk(aV[rp]) : make_float2(0.f, 0.f);
        #pragma unroll
        for (int hh = 0; hh < 2; hh++){
            int r = 2*rp + hh;
            int nd = nodes[r];
            float sv = 0.5f * (hh ? u.y : u.x);
            float o  = sv * (c0 + c1*sv + c2*sv*sv);
            if (HAS_SC) o += (hh ? v.y : v.x);
            ov[r] = o;
            if (!HAS_SC && nd >= 0){
                g_scal[nd*FD + tid] = o;
                g_agg[nd*FD + tid]  = 0.0f;     // prep for layer 1
            }
        }
    }

    // ---- fused readout ----
    if (!HAS_SC){
        float w0 = roA[tid];
        __syncthreads();
        #pragma unroll
        for (int r = 0; r < 16; r++) Wl[r*FD + tid] = ov[r]*w0;
        __syncthreads();
        int w = tid >> 5, lane = tid & 31;
        #pragma unroll
        for (int q = 0; q < 4; q++){
            int r = w*4 + q;
            float v = Wl[r*FD+lane] + Wl[r*FD+lane+32]
                    + Wl[r*FD+lane+64] + Wl[r*FD+lane+96];
            #pragma unroll
            for (int o2 = 16; o2; o2 >>= 1) v += __shfl_xor_sync(0xffffffffu, v, o2);
            if (lane == 0 && nodes[r] >= 0) out[nodes[r]*2] = v;
        }
    } else {
        __syncthreads();
        for (int i = tid; i < FD*16; i += 128) Ws[i] = roA[i];   // W1 [f][16]
        #pragma unroll
        for (int r = 0; r < 16; r++) Wl[r*FD + tid] = ov[r];
        __syncthreads();
        int rr = tid >> 3, jj = tid & 7;
        float p0 = 0.0f, p1 = 0.0f;
        #pragma unroll 4
        for (int f = 0; f < FD; f++){
            float sv = Wl[rr*FD + f];
            p0 = fmaf(sv, Ws[f*16 + jj],     p0);
            p1 = fmaf(sv, Ws[f*16 + jj + 8], p1);
        }
        float h0 = __fdividef(p0, 1.0f + __expf(-p0));
        float h1 = __fdividef(p1, 1.0f + __expf(-p1));
        float v = h0*roB[jj] + h1*roB[jj + 8];
        v += __shfl_xor_sync(0xffffffffu, v, 1);
        v += __shfl_xor_sync(0xffffffffu, v, 2);
        v += __shfl_xor_sync(0xffffffffu, v, 4);
        if (jj == 0 && nodes[rr] >= 0) out[nodes[rr]*2 + 1] = v;

        // restore invariant: cnt/cur zero for the next kernel_launch invocation
        if (blockIdx.x == 0 && tid < NSPEC){ g_cnt[tid] = 0; g_cur[tid] = 0; }
    }
}

// ---------------- launcher ---------------------------------------------------
extern "C" void kernel_launch(void* const* d_in, const int* in_sizes, int n_in,
                              void* d_out, int out_size)
{
    const float* vectors = (const float*)d_in[0];
    const int*   spec    = (const int*)  d_in[1];
    const int*   snd     = (const int*)  d_in[2];
    const int*   rcv     = (const int*)  d_in[3];
    const float* emb     = (const float*)d_in[4];
    const float* rW1     = (const float*)d_in[5];
    const float* rb1     = (const float*)d_in[6];
    const float* rW2     = (const float*)d_in[7];
    const float* linW    = (const float*)d_in[8];
    const float* pc      = (const float*)d_in[9];
    const float* scW     = (const float*)d_in[10];
    const float* ro0     = (const float*)d_in[11];
    const float* ro1W1   = (const float*)d_in[12];
    const float* ro1W2   = (const float*)d_in[13];
    float* out = (float*)d_out;

    const int LAYER_LIN  = NSPEC * 4 * FD * FD;
    const int LAYER_PC   = NSPEC * 3 * FD;

    float* w2t_ptr;  cudaGetSymbolAddress((void**)&w2t_ptr, g_w2t);

    cudaFuncSetAttribute(k_edge, cudaFuncAttributeMaxDynamicSharedMemorySize,
                         SMEM_EDGE);

    int nchunks = NN/16 + NSPEC;

    k_prep<<<1939, 256>>>(vectors, rW2, spec, emb);                  // 1 (+counts)
    k_b24<<<(NN + 255)/256, 256>>>(spec);                            // 2
    k_edge<<<GRIDE2, 256, SMEM_EDGE>>>(rW1, rb1, w2t_ptr, snd, rcv); // 3  layer 0
    k_node<false><<<nchunks, 128>>>(linW, linW, pc, ro0, ro0, out);  // 4 (+ro0)
    k_edge<<<GRIDE2, 256, SMEM_EDGE>>>(rW1 + NBASIS*NHID, rb1 + NHID,
                            w2t_ptr + NHID*FD, snd, rcv);            // 5  layer 1
    k_node<true><<<nchunks, 128>>>(linW + LAYER_LIN, scW + LAYER_LIN,
                                   pc + LAYER_PC, ro1W1, ro1W2, out);// 6 (+ro1, +cnt reset)
}

// round 15
// speedup vs baseline: 1.1005x; 1.1005x over previous
#include <cuda_runtime.h>
#include <math.h>

#define NN 10000
#define NE 160000
#define FD 128
#define NBASIS 8
#define NHID 64
#define NSPEC 10
#define NCHK2 (NE/128)               // 1250 chunks of 128 edges
#define GRIDE2 304                   // 152 SMs x 2 blocks
#define PERM_SZ (NN + 16*NSPEC)
#define RMAXF 5.0f
#define PI_F 3.14159265358979323846f
#define APITCH 18                    // Aa/As transposed pitch (even, low-conflict)

typedef unsigned long long ull;

// ---------------- device scratch (static, no allocations) ----------------
__device__ __align__(16) float g_rb[NE*NBASIS];     // radial basis per edge [E][8]
__device__ __align__(16) float g_scal[NN*FD];       // node scalar features
__device__ __align__(16) float g_agg[NN*FD];        // aggregated messages
__device__ __align__(16) float g_w2t[2*NHID*FD];    // W2 l=0 cols, transposed [layer][j][ch]
__device__ int   g_cnt[NSPEC];       // zero at module load; re-zeroed by k_node<true>
__device__ int   g_cur[NSPEC];
__device__ int   g_off[NSPEC+1];
__device__ int   g_perm[PERM_SZ];

// ---------------- f32x2 / vector-red helpers --------------------------------
__device__ __forceinline__ ull dup2(float w){
    ull r; asm("mov.b64 %0, {%1, %1};" : "=l"(r) : "f"(w)); return r;
}
__device__ __forceinline__ void ffma2(ull& acc, ull a, ull b){
    asm("fma.rn.f32x2 %0, %1, %2, %0;" : "+l"(acc) : "l"(a), "l"(b));
}
__device__ __forceinline__ float2 unpk(ull v){
    float2 r; asm("mov.b64 {%0, %1}, %2;" : "=f"(r.x), "=f"(r.y) : "l"(v)); return r;
}
__device__ __forceinline__ void red4(float* p, float a, float b, float c, float d){
    asm volatile("red.global.add.v4.f32 [%0], {%1,%2,%3,%4};"
                 :: "l"(p), "f"(a), "f"(b), "f"(c), "f"(d) : "memory");
}

// ---------------- k_prep: w2t + perm init | geom | scal/agg init + counts ---
__global__ void k_prep(const float* __restrict__ vec, const float* __restrict__ W2,
                       const int* __restrict__ spec, const float* __restrict__ emb){
    int b = blockIdx.x;
    if (b < 64){
        int idx = b*256 + threadIdx.x;
        if (idx < 2*NHID*FD){
            int l = idx >> 13, rem = idx & 8191;
            int j = rem >> 7, ch = rem & 127;
            g_w2t[idx] = W2[l*NHID*FD*4 + j*FD*4 + ch*4];
        }
        if (idx < PERM_SZ) g_perm[idx] = -1;
    } else if (b < 689){
        int e = (b - 64)*256 + threadIdx.x;
        float x = vec[3*e+0], y = vec[3*e+1], z = vec[3*e+2];
        float r = sqrtf(x*x + y*y + z*z);
        r = fmaxf(r, 1e-9f);
        float rc  = fminf(r, RMAXF);
        float cut = 0.5f*(__cosf(PI_F*rc/RMAXF) + 1.0f);
        float pref = sqrtf(2.0f/RMAXF) / r * cut;
        float arg = PI_F * r / RMAXF;
        float s1 = __sinf(arg), c2 = 2.0f*__cosf(arg);
        float v[NBASIS];
        float sm1 = 0.0f, s = s1;
        #pragma unroll
        for (int n = 0; n < NBASIS; n++){
            v[n] = pref * s;
            float sn = c2*s - sm1;
            sm1 = s; s = sn;
        }
        float4* dst = (float4*)&g_rb[(size_t)e*NBASIS];
        dst[0] = make_float4(v[0], v[1], v[2], v[3]);
        dst[1] = make_float4(v[4], v[5], v[6], v[7]);
    } else {
        int idx = (b - 689)*256 + threadIdx.x;
        int n = idx >> 5, f4 = idx & 31;
        int s = spec[n];
        ((float4*)g_scal)[idx] = ((const float4*)emb)[s*32 + f4];
        ((float4*)g_agg)[idx]  = make_float4(0.f, 0.f, 0.f, 0.f);
        if (f4 == 0) atomicAdd(&g_cnt[s], 1);
    }
}

// ---------------- merged offsets + placement ---------------------------------
__global__ void k_b24(const int* __restrict__ spec){
    __shared__ int offs[NSPEC];
    if (threadIdx.x == 0){
        int o = 0;
        #pragma unroll
        for (int s = 0; s < NSPEC; s++){ offs[s] = o; o += (g_cnt[s] + 15) & ~15; }
        if (blockIdx.x == 0){
            #pragma unroll
            for (int s = 0; s < NSPEC; s++) g_off[s] = offs[s];
            g_off[NSPEC] = o;
        }
    }
    __syncthreads();
    int n = blockIdx.x*256 + threadIdx.x;
    if (n < NN){
        int s = spec[n];
        int p = atomicAdd(&g_cur[s], 1);
        g_perm[offs[s] + p] = n;
    }
}

// ---------------- fused edge kernel (R13-proven) ------------------------------
// 304 blocks x 256 threads; 8 warps = (4 edge-quarters of 32e) x (2 ch-halves).
// Warp GEMM tile: 32 edges x 64 ch; lane: 8 edges x 8 ch (1.0 B/MAC LDS).
__global__ __launch_bounds__(256, 2) void k_edge(
    const float* __restrict__ W1, const float* __restrict__ b1,
    const float* __restrict__ W2t,
    const int* __restrict__ snd, const int* __restrict__ rcv)
{
    __shared__ float W2c[NHID*FD];          // 32 KB
    __shared__ float W1s[NBASIS*NHID];
    __shared__ float b1s[NHID];
    __shared__ float rb_s[128*9];
    __shared__ float h_t[NHID*132];         // [j][edge 0..127], pitch 132
    __shared__ int   snd_s[128], rcv_s[128];
    int tid = threadIdx.x, lane = tid & 31, w = tid >> 5;

    {   // stage weights once per block
        const float4* src = (const float4*)W2t;
        float4* dst = (float4*)W2c;
        #pragma unroll
        for (int i = 0; i < 8; i++) dst[tid + i*256] = src[tid + i*256];
    }
    for (int i = tid; i < NBASIS*NHID; i += 256) W1s[i] = W1[i];
    if (tid < NHID) b1s[tid] = b1[tid];

    int eq = w & 3, chalf = w >> 2;
    int cg = lane >> 2, eg = lane & 3;
    int ch0 = chalf*64 + cg*4;
    int eb0 = eq*32 + eg*8;                 // lane's first edge within chunk

    int ck = blockIdx.x;
    float2 pf0, pf1; int pf_idx = 0;
    {   // prefetch chunk ck
        int e0 = ck*128;
        pf0 = ((const float2*)g_rb)[e0*4 + tid];
        pf1 = ((const float2*)g_rb)[e0*4 + 256 + tid];
        pf_idx = (tid < 128) ? snd[e0 + tid] : rcv[e0 + tid - 128];
    }

    while (ck < NCHK2){
        __syncthreads();                    // prev chunk smem readers done
        {   int i0 = tid*2;
            int o0 = (i0 >> 3)*9 + (i0 & 7);
            rb_s[o0]   = pf0.x;  rb_s[o0+1] = pf0.y;
            int i1 = i0 + 512;
            int o1 = (i1 >> 3)*9 + (i1 & 7);
            rb_s[o1]   = pf1.x;  rb_s[o1+1] = pf1.y;
            if (tid < 128) snd_s[tid] = pf_idx;
            else           rcv_s[tid-128] = pf_idx;
        }
        __syncthreads();

        // ---- h = silu(rb @ W1 + b1), h_t[j][e]; warp w owns j in [8w,8w+8) --
        #pragma unroll
        for (int sub = 0; sub < 4; sub++){
            int he = lane + sub*32;
            float rbv[NBASIS];
            #pragma unroll
            for (int k = 0; k < NBASIS; k++) rbv[k] = rb_s[he*9 + k];
            #pragma unroll
            for (int q = 0; q < 8; q++){
                int j = w*8 + q;
                float a = b1s[j];
                #pragma unroll
                for (int k = 0; k < NBASIS; k++)
                    a = fmaf(rbv[k], W1s[k*NHID + j], a);
                h_t[j*132 + he] = __fdividef(a, 1.0f + __expf(-a));
            }
        }
        __syncthreads();

        // ---- prefetch next chunk (overlaps GEMM below) ----
        int ckn = ck + GRIDE2;
        if (ckn < NCHK2){
            int e0n = ckn*128;
            pf0 = ((const float2*)g_rb)[e0n*4 + tid];
            pf1 = ((const float2*)g_rb)[e0n*4 + 256 + tid];
            pf_idx = (tid < 128) ? snd[e0n + tid] : rcv[e0n + tid - 128];
        }

        // ---- rw0 = h @ W2c : 32e x 64ch register tile ----
        ull acc[8][4];                      // [ch-slot][edge-pair]
        #pragma unroll
        for (int c = 0; c < 8; c++)
            #pragma unroll
            for (int p = 0; p < 4; p++) acc[c][p] = 0ULL;

        #pragma unroll 2
        for (int j = 0; j < NHID; j++){
            float4 wa = *(const float4*)&W2c[j*FD + ch0];
            float4 wb = *(const float4*)&W2c[j*FD + ch0 + 32];
            ulonglong2 ha = *(const ulonglong2*)&h_t[j*132 + eb0];
            ulonglong2 hb = *(const ulonglong2*)&h_t[j*132 + eb0 + 4];
            ull wd0 = dup2(wa.x), wd1 = dup2(wa.y), wd2 = dup2(wa.z), wd3 = dup2(wa.w);
            ull wd4 = dup2(wb.x), wd5 = dup2(wb.y), wd6 = dup2(wb.z), wd7 = dup2(wb.w);
            ffma2(acc[0][0], ha.x, wd0); ffma2(acc[0][1], ha.y, wd0);
            ffma2(acc[0][2], hb.x, wd0); ffma2(acc[0][3], hb.y, wd0);
            ffma2(acc[1][0], ha.x, wd1); ffma2(acc[1][1], ha.y, wd1);
            ffma2(acc[1][2], hb.x, wd1); ffma2(acc[1][3], hb.y, wd1);
            ffma2(acc[2][0], ha.x, wd2); ffma2(acc[2][1], ha.y, wd2);
            ffma2(acc[2][2], hb.x, wd2); ffma2(acc[2][3], hb.y, wd2);
            ffma2(acc[3][0], ha.x, wd3); ffma2(acc[3][1], ha.y, wd3);
            ffma2(acc[3][2], hb.x, wd3); ffma2(acc[3][3], hb.y, wd3);
            ffma2(acc[4][0], ha.x, wd4); ffma2(acc[4][1], ha.y, wd4);
            ffma2(acc[4][2], hb.x, wd4); ffma2(acc[4][3], hb.y, wd4);
            ffma2(acc[5][0], ha.x, wd5); ffma2(acc[5][1], ha.y, wd5);
            ffma2(acc[5][2], hb.x, wd5); ffma2(acc[5][3], hb.y, wd5);
            ffma2(acc[6][0], ha.x, wd6); ffma2(acc[6][1], ha.y, wd6);
            ffma2(acc[6][2], hb.x, wd6); ffma2(acc[6][3], hb.y, wd6);
            ffma2(acc[7][0], ha.x, wd7); ffma2(acc[7][1], ha.y, wd7);
            ffma2(acc[7][2], hb.x, wd7); ffma2(acc[7][3], hb.y, wd7);
        }

        // ---- unpack + scatter: lane owns 8 edges x 8 ch ----
        #pragma unroll
        for (int p = 0; p < 4; p++){
            float2 m0 = unpk(acc[0][p]), m1 = unpk(acc[1][p]);
            float2 m2 = unpk(acc[2][p]), m3 = unpk(acc[3][p]);
            float2 m4 = unpk(acc[4][p]), m5 = unpk(acc[5][p]);
            float2 m6 = unpk(acc[6][p]), m7 = unpk(acc[7][p]);
            int ea = eb0 + 2*p, eb = ea + 1;
            {
                int sidx = snd_s[ea], ridx = rcv_s[ea];
                float4 ssa = *(const float4*)&g_scal[sidx*FD + ch0];
                float4 ssb = *(const float4*)&g_scal[sidx*FD + ch0 + 32];
                red4(&g_agg[ridx*FD + ch0],
                     m0.x*ssa.x, m1.x*ssa.y, m2.x*ssa.z, m3.x*ssa.w);
                red4(&g_agg[ridx*FD + ch0 + 32],
                     m4.x*ssb.x, m5.x*ssb.y, m6.x*ssb.z, m7.x*ssb.w);
            }
            {
                int sidx = snd_s[eb], ridx = rcv_s[eb];
                float4 ssa = *(const float4*)&g_scal[sidx*FD + ch0];
                float4 ssb = *(const float4*)&g_scal[sidx*FD + ch0 + 32];
                red4(&g_agg[ridx*FD + ch0],
                     m0.y*ssa.x, m1.y*ssa.y, m2.y*ssa.z, m3.y*ssa.w);
                red4(&g_agg[ridx*FD + ch0 + 32],
                     m4.y*ssb.x, m5.y*ssb.y, m6.y*ssb.z, m7.y*ssb.w);
            }
        }
        ck = ckn;
    }
}

// ---------------- fused node kernel + readout (transposed-tile LDS.64) -------
// Aa/As stored [ftl][r] with pitch 18: packed r-pairs load as one LDS.64
// broadcast -> inner loop is 1 LDS.64 + 1 FFMA2 per (ft, r-pair).
template<bool HAS_SC>
__global__ __launch_bounds__(128) void k_node(
    const float* __restrict__ linW,
    const float* __restrict__ scWp,
    const float* __restrict__ pc,
    const float* __restrict__ roA,      // ro0W (L0) / ro1W1 (L1)
    const float* __restrict__ roB,      // unused (L0) / ro1W2 (L1)
    float* __restrict__ out)
{
    int tid = threadIdx.x;
    int c16 = blockIdx.x * 16;
    if (c16 >= g_off[NSPEC]) return;
    int s = 0;
    while (c16 >= g_off[s+1]) s++;

    __shared__ int   nodes[16];
    __shared__ float Wl[16*FD];
    __shared__ float Ws[16*FD];
    __shared__ float Aa[16*APITCH];     // [ftl][r]
    __shared__ float As[16*APITCH];
    if (tid < 16) nodes[tid] = g_perm[c16 + tid];

    ull aU[8], aV[8];
    #pragma unroll
    for (int rp = 0; rp < 8; rp++){ aU[rp] = 0ULL; aV[rp] = 0ULL; }

    const float* WL = linW + (size_t)s * 4 * FD * FD;
    const float* WS = HAS_SC ? (scWp + (size_t)s * 4 * FD * FD) : linW;

    for (int ft0 = 0; ft0 < FD; ft0 += 16){
        __syncthreads();
        for (int i = tid; i < 16*FD; i += 128){
            int r = i >> 7, gg = i & 127;
            Wl[i] = WL[(ft0 + r)*FD + gg];
            if (HAS_SC) Ws[i] = WS[(ft0 + r)*FD + gg];
        }
        for (int i = tid; i < 256; i += 128){
            int r = i >> 4, ftl = i & 15, nd = nodes[r];
            int fc = ft0 + ftl;
            Aa[ftl*APITCH + r] = (nd < 0) ? 0.0f : g_agg[nd*FD + fc];
            if (HAS_SC) As[ftl*APITCH + r] = (nd < 0) ? 0.0f : g_scal[nd*FD + fc];
        }
        __syncthreads();
        #pragma unroll 4
        for (int ft = 0; ft < 16; ft++){
            ull wld = dup2(Wl[ft*FD + tid]);
            const ull* ap = (const ull*)&Aa[ft*APITCH];
            if (HAS_SC){
                ull wsd = dup2(Ws[ft*FD + tid]);
                const ull* sp = (const ull*)&As[ft*APITCH];
                #pragma unroll
                for (int rp = 0; rp < 8; rp++){
                    ffma2(aU[rp], ap[rp], wld);
                    ffma2(aV[rp], sp[rp], wsd);
                }
            } else {
                #pragma unroll
                for (int rp = 0; rp < 8; rp++)
                    ffma2(aU[rp], ap[rp], wld);
            }
        }
    }
    const float* C = pc + s*3*FD;
    float c0 = C[tid], c1 = C[FD + tid], c2 = C[2*FD + tid];
    float ov[16];
    #pragma unroll
    for (int rp = 0; rp < 8; rp++){
        float2 u = unpk(aU[rp]);
        float2 v = HAS_SC ? unpk(aV[rp]) : make_float2(0.f, 0.f);
        #pragma unroll
        for (int hh = 0; hh < 2; hh++){
            int r = 2*rp + hh;
            int nd = nodes[r];
            float sv = 0.5f * (hh ? u.y : u.x);
            float o  = sv * (c0 + c1*sv + c2*sv*sv);
            if (HAS_SC) o += (hh ? v.y : v.x);
            ov[r] = o;
            if (!HAS_SC && nd >= 0){
                g_scal[nd*FD + tid] = o;
                g_agg[nd*FD + tid]  = 0.0f;     // prep for layer 1
            }
        }
    }

    // ---- fused readout ----
    if (!HAS_SC){
        float w0 = roA[tid];
        __syncthreads();
        #pragma unroll
        for (int r = 0; r < 16; r++) Wl[r*FD + tid] = ov[r]*w0;
        __syncthreads();
        int w = tid >> 5, lane = tid & 31;
        #pragma unroll
        for (int q = 0; q < 4; q++){
            int r = w*4 + q;
            float v = Wl[r*FD+lane] + Wl[r*FD+lane+32]
                    + Wl[r*FD+lane+64] + Wl[r*FD+lane+96];
            #pragma unroll
            for (int o2 = 16; o2; o2 >>= 1) v += __shfl_xor_sync(0xffffffffu, v, o2);
            if (lane == 0 && nodes[r] >= 0) out[nodes[r]*2] = v;
        }
    } else {
        __syncthreads();
        for (int i = tid; i < FD*16; i += 128) Ws[i] = roA[i];   // W1 [f][16]
        #pragma unroll
        for (int r = 0; r < 16; r++) Wl[r*FD + tid] = ov[r];
        __syncthreads();
        int rr = tid >> 3, jj = tid & 7;
        float p0 = 0.0f, p1 = 0.0f;
        #pragma unroll 4
        for (int f = 0; f < FD; f++){
            float sv = Wl[rr*FD + f];
            p0 = fmaf(sv, Ws[f*16 + jj],     p0);
            p1 = fmaf(sv, Ws[f*16 + jj + 8], p1);
        }
        float h0 = __fdividef(p0, 1.0f + __expf(-p0));
        float h1 = __fdividef(p1, 1.0f + __expf(-p1));
        float v = h0*roB[jj] + h1*roB[jj + 8];
        v += __shfl_xor_sync(0xffffffffu, v, 1);
        v += __shfl_xor_sync(0xffffffffu, v, 2);
        v += __shfl_xor_sync(0xffffffffu, v, 4);
        if (jj == 0 && nodes[rr] >= 0) out[nodes[rr]*2 + 1] = v;

        // restore invariant: cnt/cur zero for the next kernel_launch invocation
        if (blockIdx.x == 0 && tid < NSPEC){ g_cnt[tid] = 0; g_cur[tid] = 0; }
    }
}

// ---------------- launcher ---------------------------------------------------
extern "C" void kernel_launch(void* const* d_in, const int* in_sizes, int n_in,
                              void* d_out, int out_size)
{
    const float* vectors = (const float*)d_in[0];
    const int*   spec    = (const int*)  d_in[1];
    const int*   snd     = (const int*)  d_in[2];
    const int*   rcv     = (const int*)  d_in[3];
    const float* emb     = (const float*)d_in[4];
    const float* rW1     = (const float*)d_in[5];
    const float* rb1     = (const float*)d_in[6];
    const float* rW2     = (const float*)d_in[7];
    const float* linW    = (const float*)d_in[8];
    const float* pc      = (const float*)d_in[9];
    const float* scW     = (const float*)d_in[10];
    const float* ro0     = (const float*)d_in[11];
    const float* ro1W1   = (const float*)d_in[12];
    const float* ro1W2   = (const float*)d_in[13];
    float* out = (float*)d_out;

    const int LAYER_LIN  = NSPEC * 4 * FD * FD;
    const int LAYER_PC   = NSPEC * 3 * FD;

    float* w2t_ptr;  cudaGetSymbolAddress((void**)&w2t_ptr, g_w2t);

    int nchunks = NN/16 + NSPEC;

    k_prep<<<1939, 256>>>(vectors, rW2, spec, emb);                  // 1 (+counts)
    k_b24<<<(NN + 255)/256, 256>>>(spec);                            // 2
    k_edge<<<GRIDE2, 256>>>(rW1, rb1, w2t_ptr, snd, rcv);            // 3  layer 0
    k_node<false><<<nchunks, 128>>>(linW, linW, pc, ro0, ro0, out);  // 4 (+ro0)
    k_edge<<<GRIDE2, 256>>>(rW1 + NBASIS*NHID, rb1 + NHID,
                            w2t_ptr + NHID*FD, snd, rcv);            // 5  layer 1
    k_node<true><<<nchunks, 128>>>(linW + LAYER_LIN, scW + LAYER_LIN,
                                   pc + LAYER_PC, ro1W1, ro1W2, out);// 6 (+ro1, +cnt reset)
}

// round 16
// speedup vs baseline: 1.1729x; 1.0658x over previous
#include <cuda_runtime.h>
#include <math.h>

#define NN 10000
#define NE 160000
#define FD 128
#define NBASIS 8
#define NHID 64
#define NSPEC 10
#define NCHK2 (NE/128)               // 1250 chunks of 128 edges
#define GRIDE2 304                   // 152 SMs x 2 blocks
#define PERM_SZ (NN + 16*NSPEC)
#define RMAXF 5.0f
#define PI_F 3.14159265358979323846f
#define APITCH 18                    // Aa/As transposed pitch (even, low-conflict)

typedef unsigned long long ull;

// ---------------- device scratch (static, no allocations) ----------------
__device__ __align__(16) float g_rb[NE*NBASIS];     // radial basis per edge [E][8]
__device__ __align__(16) float g_scal[NN*FD];       // node scalar features
__device__ __align__(16) float g_agg[NN*FD];        // aggregated messages
__device__ __align__(16) float g_w2t[2*NHID*FD];    // W2 l=0 cols, transposed [layer][j][ch]
__device__ int   g_cnt[NSPEC];       // zero at module load; re-zeroed by k_node<true>
__device__ int   g_cur[NSPEC];
__device__ int   g_off[NSPEC+1];
__device__ int   g_perm[PERM_SZ];

// ---------------- f32x2 / vector-red helpers --------------------------------
__device__ __forceinline__ ull dup2(float w){
    ull r; asm("mov.b64 %0, {%1, %1};" : "=l"(r) : "f"(w)); return r;
}
__device__ __forceinline__ void ffma2(ull& acc, ull a, ull b){
    asm("fma.rn.f32x2 %0, %1, %2, %0;" : "+l"(acc) : "l"(a), "l"(b));
}
__device__ __forceinline__ float2 unpk(ull v){
    float2 r; asm("mov.b64 {%0, %1}, %2;" : "=f"(r.x), "=f"(r.y) : "l"(v)); return r;
}
__device__ __forceinline__ void red4(float* p, float a, float b, float c, float d){
    asm volatile("red.global.add.v4.f32 [%0], {%1,%2,%3,%4};"
                 :: "l"(p), "f"(a), "f"(b), "f"(c), "f"(d) : "memory");
}

// ---------------- k_prep: w2t + perm init | geom | scal/agg init + counts ---
__global__ void k_prep(const float* __restrict__ vec, const float* __restrict__ W2,
                       const int* __restrict__ spec, const float* __restrict__ emb){
    int b = blockIdx.x;
    if (b < 64){
        int idx = b*256 + threadIdx.x;
        if (idx < 2*NHID*FD){
            int l = idx >> 13, rem = idx & 8191;
            int j = rem >> 7, ch = rem & 127;
            g_w2t[idx] = W2[l*NHID*FD*4 + j*FD*4 + ch*4];
        }
        if (idx < PERM_SZ) g_perm[idx] = -1;
    } else if (b < 689){
        int e = (b - 64)*256 + threadIdx.x;
        float x = vec[3*e+0], y = vec[3*e+1], z = vec[3*e+2];
        float r = sqrtf(x*x + y*y + z*z);
        r = fmaxf(r, 1e-9f);
        float rc  = fminf(r, RMAXF);
        float cut = 0.5f*(__cosf(PI_F*rc/RMAXF) + 1.0f);
        float pref = sqrtf(2.0f/RMAXF) / r * cut;
        float arg = PI_F * r / RMAXF;
        float s1 = __sinf(arg), c2 = 2.0f*__cosf(arg);
        float v[NBASIS];
        float sm1 = 0.0f, s = s1;
        #pragma unroll
        for (int n = 0; n < NBASIS; n++){
            v[n] = pref * s;
            float sn = c2*s - sm1;
            sm1 = s; s = sn;
        }
        float4* dst = (float4*)&g_rb[(size_t)e*NBASIS];
        dst[0] = make_float4(v[0], v[1], v[2], v[3]);
        dst[1] = make_float4(v[4], v[5], v[6], v[7]);
    } else {
        int idx = (b - 689)*256 + threadIdx.x;
        int n = idx >> 5, f4 = idx & 31;
        int s = spec[n];
        ((float4*)g_scal)[idx] = ((const float4*)emb)[s*32 + f4];
        ((float4*)g_agg)[idx]  = make_float4(0.f, 0.f, 0.f, 0.f);
        if (f4 == 0) atomicAdd(&g_cnt[s], 1);
    }
}

// ---------------- merged offsets + placement ---------------------------------
__global__ void k_b24(const int* __restrict__ spec){
    __shared__ int offs[NSPEC];
    if (threadIdx.x == 0){
        int o = 0;
        #pragma unroll
        for (int s = 0; s < NSPEC; s++){ offs[s] = o; o += (g_cnt[s] + 15) & ~15; }
        if (blockIdx.x == 0){
            #pragma unroll
            for (int s = 0; s < NSPEC; s++) g_off[s] = offs[s];
            g_off[NSPEC] = o;
        }
    }
    __syncthreads();
    int n = blockIdx.x*256 + threadIdx.x;
    if (n < NN){
        int s = spec[n];
        int p = atomicAdd(&g_cur[s], 1);
        g_perm[offs[s] + p] = n;
    }
}

// ---------------- fused edge kernel (R13-proven, unchanged) -------------------
__global__ __launch_bounds__(256, 2) void k_edge(
    const float* __restrict__ W1, const float* __restrict__ b1,
    const float* __restrict__ W2t,
    const int* __restrict__ snd, const int* __restrict__ rcv)
{
    __shared__ float W2c[NHID*FD];          // 32 KB
    __shared__ float W1s[NBASIS*NHID];
    __shared__ float b1s[NHID];
    __shared__ float rb_s[128*9];
    __shared__ float h_t[NHID*132];         // [j][edge 0..127], pitch 132
    __shared__ int   snd_s[128], rcv_s[128];
    int tid = threadIdx.x, lane = tid & 31, w = tid >> 5;

    {   // stage weights once per block
        const float4* src = (const float4*)W2t;
        float4* dst = (float4*)W2c;
        #pragma unroll
        for (int i = 0; i < 8; i++) dst[tid + i*256] = src[tid + i*256];
    }
    for (int i = tid; i < NBASIS*NHID; i += 256) W1s[i] = W1[i];
    if (tid < NHID) b1s[tid] = b1[tid];

    int eq = w & 3, chalf = w >> 2;
    int cg = lane >> 2, eg = lane & 3;
    int ch0 = chalf*64 + cg*4;
    int eb0 = eq*32 + eg*8;                 // lane's first edge within chunk

    int ck = blockIdx.x;
    float2 pf0, pf1; int pf_idx = 0;
    {   // prefetch chunk ck
        int e0 = ck*128;
        pf0 = ((const float2*)g_rb)[e0*4 + tid];
        pf1 = ((const float2*)g_rb)[e0*4 + 256 + tid];
        pf_idx = (tid < 128) ? snd[e0 + tid] : rcv[e0 + tid - 128];
    }

    while (ck < NCHK2){
        __syncthreads();                    // prev chunk smem readers done
        {   int i0 = tid*2;
            int o0 = (i0 >> 3)*9 + (i0 & 7);
            rb_s[o0]   = pf0.x;  rb_s[o0+1] = pf0.y;
            int i1 = i0 + 512;
            int o1 = (i1 >> 3)*9 + (i1 & 7);
            rb_s[o1]   = pf1.x;  rb_s[o1+1] = pf1.y;
            if (tid < 128) snd_s[tid] = pf_idx;
            else           rcv_s[tid-128] = pf_idx;
        }
        __syncthreads();

        // ---- h = silu(rb @ W1 + b1), h_t[j][e]; warp w owns j in [8w,8w+8) --
        #pragma unroll
        for (int sub = 0; sub < 4; sub++){
            int he = lane + sub*32;
            float rbv[NBASIS];
            #pragma unroll
            for (int k = 0; k < NBASIS; k++) rbv[k] = rb_s[he*9 + k];
            #pragma unroll
            for (int q = 0; q < 8; q++){
                int j = w*8 + q;
                float a = b1s[j];
                #pragma unroll
                for (int k = 0; k < NBASIS; k++)
                    a = fmaf(rbv[k], W1s[k*NHID + j], a);
                h_t[j*132 + he] = __fdividef(a, 1.0f + __expf(-a));
            }
        }
        __syncthreads();

        // ---- prefetch next chunk (overlaps GEMM below) ----
        int ckn = ck + GRIDE2;
        if (ckn < NCHK2){
            int e0n = ckn*128;
            pf0 = ((const float2*)g_rb)[e0n*4 + tid];
            pf1 = ((const float2*)g_rb)[e0n*4 + 256 + tid];
            pf_idx = (tid < 128) ? snd[e0n + tid] : rcv[e0n + tid - 128];
        }

        // ---- rw0 = h @ W2c : 32e x 64ch register tile ----
        ull acc[8][4];                      // [ch-slot][edge-pair]
        #pragma unroll
        for (int c = 0; c < 8; c++)
            #pragma unroll
            for (int p = 0; p < 4; p++) acc[c][p] = 0ULL;

        #pragma unroll 2
        for (int j = 0; j < NHID; j++){
            float4 wa = *(const float4*)&W2c[j*FD + ch0];
            float4 wb = *(const float4*)&W2c[j*FD + ch0 + 32];
            ulonglong2 ha = *(const ulonglong2*)&h_t[j*132 + eb0];
            ulonglong2 hb = *(const ulonglong2*)&h_t[j*132 + eb0 + 4];
            ull wd0 = dup2(wa.x), wd1 = dup2(wa.y), wd2 = dup2(wa.z), wd3 = dup2(wa.w);
            ull wd4 = dup2(wb.x), wd5 = dup2(wb.y), wd6 = dup2(wb.z), wd7 = dup2(wb.w);
            ffma2(acc[0][0], ha.x, wd0); ffma2(acc[0][1], ha.y, wd0);
            ffma2(acc[0][2], hb.x, wd0); ffma2(acc[0][3], hb.y, wd0);
            ffma2(acc[1][0], ha.x, wd1); ffma2(acc[1][1], ha.y, wd1);
            ffma2(acc[1][2], hb.x, wd1); ffma2(acc[1][3], hb.y, wd1);
            ffma2(acc[2][0], ha.x, wd2); ffma2(acc[2][1], ha.y, wd2);
            ffma2(acc[2][2], hb.x, wd2); ffma2(acc[2][3], hb.y, wd2);
            ffma2(acc[3][0], ha.x, wd3); ffma2(acc[3][1], ha.y, wd3);
            ffma2(acc[3][2], hb.x, wd3); ffma2(acc[3][3], hb.y, wd3);
            ffma2(acc[4][0], ha.x, wd4); ffma2(acc[4][1], ha.y, wd4);
            ffma2(acc[4][2], hb.x, wd4); ffma2(acc[4][3], hb.y, wd4);
            ffma2(acc[5][0], ha.x, wd5); ffma2(acc[5][1], ha.y, wd5);
            ffma2(acc[5][2], hb.x, wd5); ffma2(acc[5][3], hb.y, wd5);
            ffma2(acc[6][0], ha.x, wd6); ffma2(acc[6][1], ha.y, wd6);
            ffma2(acc[6][2], hb.x, wd6); ffma2(acc[6][3], hb.y, wd6);
            ffma2(acc[7][0], ha.x, wd7); ffma2(acc[7][1], ha.y, wd7);
            ffma2(acc[7][2], hb.x, wd7); ffma2(acc[7][3], hb.y, wd7);
        }

        // ---- unpack + scatter: lane owns 8 edges x 8 ch ----
        #pragma unroll
        for (int p = 0; p < 4; p++){
            float2 m0 = unpk(acc[0][p]), m1 = unpk(acc[1][p]);
            float2 m2 = unpk(acc[2][p]), m3 = unpk(acc[3][p]);
            float2 m4 = unpk(acc[4][p]), m5 = unpk(acc[5][p]);
            float2 m6 = unpk(acc[6][p]), m7 = unpk(acc[7][p]);
            int ea = eb0 + 2*p, eb = ea + 1;
            {
                int sidx = snd_s[ea], ridx = rcv_s[ea];
                float4 ssa = *(const float4*)&g_scal[sidx*FD + ch0];
                float4 ssb = *(const float4*)&g_scal[sidx*FD + ch0 + 32];
                red4(&g_agg[ridx*FD + ch0],
                     m0.x*ssa.x, m1.x*ssa.y, m2.x*ssa.z, m3.x*ssa.w);
                red4(&g_agg[ridx*FD + ch0 + 32],
                     m4.x*ssb.x, m5.x*ssb.y, m6.x*ssb.z, m7.x*ssb.w);
            }
            {
                int sidx = snd_s[eb], ridx = rcv_s[eb];
                float4 ssa = *(const float4*)&g_scal[sidx*FD + ch0];
                float4 ssb = *(const float4*)&g_scal[sidx*FD + ch0 + 32];
                red4(&g_agg[ridx*FD + ch0],
                     m0.y*ssa.x, m1.y*ssa.y, m2.y*ssa.z, m3.y*ssa.w);
                red4(&g_agg[ridx*FD + ch0 + 32],
                     m4.y*ssb.x, m5.y*ssb.y, m6.y*ssb.z, m7.y*ssb.w);
            }
        }
        ck = ckn;
    }
}

// ---------------- fused node kernel + readout (pipelined GEMV) ---------------
// Weights register-resident (direct coalesced LDG, prefetched 1 tile ahead);
// Aa/As prefetched 1 tile ahead into regs, staged to transposed smem tile.
// Inner loop: 1 LDS.64 broadcast + 1 FFMA2 per (ft, r-pair).
template<bool HAS_SC>
__global__ __launch_bounds__(128) void k_node(
    const float* __restrict__ linW,
    const float* __restrict__ scWp,
    const float* __restrict__ pc,
    const float* __restrict__ roA,      // ro0W (L0) / ro1W1 (L1)
    const float* __restrict__ roB,      // unused (L0) / ro1W2 (L1)
    float* __restrict__ out)
{
    int tid = threadIdx.x;
    int c16 = blockIdx.x * 16;
    if (c16 >= g_off[NSPEC]) return;
    int s = 0;
    while (c16 >= g_off[s+1]) s++;

    __shared__ int   nodes[16];
    __shared__ float Wl[16*FD];         // readout scratch only
    __shared__ float Ws[16*FD];         // readout scratch only (L1 W1)
    __shared__ float Aa[16*APITCH];     // [ftl][r]
    __shared__ float As[16*APITCH];
    if (tid < 16) nodes[tid] = g_perm[c16 + tid];

    ull aU[8], aV[8];
    #pragma unroll
    for (int rp = 0; rp < 8; rp++){ aU[rp] = 0ULL; aV[rp] = 0ULL; }

    const float* WL = linW + (size_t)s * 4 * FD * FD;
    const float* WS = HAS_SC ? (scWp + (size_t)s * 4 * FD * FD) : linW;

    __syncthreads();                    // nodes[] visible

    // prefetch registers: tile weights + Aa/As entries (2 per thread)
    int r_a = tid >> 4, ftl_a = tid & 15;           // entry 0: i = tid
    int r_b = (tid + 128) >> 4, ftl_b = tid & 15;   // entry 1: i = tid+128
    int nd_a = nodes[r_a], nd_b = nodes[r_b];

    float wcur[16], wscur[16];
    #pragma unroll
    for (int r = 0; r < 16; r++){
        wcur[r] = WL[r*FD + tid];
        if (HAS_SC) wscur[r] = WS[r*FD + tid];
    }
    float apf0 = (nd_a < 0) ? 0.0f : g_agg[nd_a*FD + ftl_a];
    float apf1 = (nd_b < 0) ? 0.0f : g_agg[nd_b*FD + ftl_b];
    float spf0 = 0.0f, spf1 = 0.0f;
    if (HAS_SC){
        spf0 = (nd_a < 0) ? 0.0f : g_scal[nd_a*FD + ftl_a];
        spf1 = (nd_b < 0) ? 0.0f : g_scal[nd_b*FD + ftl_b];
    }

    #pragma unroll 1
    for (int ft0 = 0; ft0 < FD; ft0 += 16){
        __syncthreads();                // prev tile's Aa reads done
        Aa[ftl_a*APITCH + r_a] = apf0;
        Aa[ftl_b*APITCH + r_b] = apf1;
        if (HAS_SC){
            As[ftl_a*APITCH + r_a] = spf0;
            As[ftl_b*APITCH + r_b] = spf1;
        }
        __syncthreads();

        // prefetch next tile (overlaps compute)
        float wnxt[16], wsnxt[16];
        if (ft0 + 16 < FD){
            int fn = ft0 + 16;
            #pragma unroll
            for (int r = 0; r < 16; r++){
                wnxt[r] = WL[(fn + r)*FD + tid];
                if (HAS_SC) wsnxt[r] = WS[(fn + r)*FD + tid];
            }
            apf0 = (nd_a < 0) ? 0.0f : g_agg[nd_a*FD + fn + ftl_a];
            apf1 = (nd_b < 0) ? 0.0f : g_agg[nd_b*FD + fn + ftl_b];
            if (HAS_SC){
                spf0 = (nd_a < 0) ? 0.0f : g_scal[nd_a*FD + fn + ftl_a];
                spf1 = (nd_b < 0) ? 0.0f : g_scal[nd_b*FD + fn + ftl_b];
            }
        }

        // compute tile
        #pragma unroll
        for (int ft = 0; ft < 16; ft++){
            ull wld = dup2(wcur[ft]);
            const ull* ap = (const ull*)&Aa[ft*APITCH];
            if (HAS_SC){
                ull wsd = dup2(wscur[ft]);
                const ull* sp = (const ull*)&As[ft*APITCH];
                #pragma unroll
                for (int rp = 0; rp < 8; rp++){
                    ffma2(aU[rp], ap[rp], wld);
                    ffma2(aV[rp], sp[rp], wsd);
                }
            } else {
                #pragma unroll
                for (int rp = 0; rp < 8; rp++)
                    ffma2(aU[rp], ap[rp], wld);
            }
        }
        #pragma unroll
        for (int r = 0; r < 16; r++){
            wcur[r] = wnxt[r];
            if (HAS_SC) wscur[r] = wsnxt[r];
        }
    }

    const float* C = pc + s*3*FD;
    float c0 = C[tid], c1 = C[FD + tid], c2 = C[2*FD + tid];
    float ov[16];
    #pragma unroll
    for (int rp = 0; rp < 8; rp++){
        float2 u = unpk(aU[rp]);
        float2 v = HAS_SC ? unpk(aV[rp]) : make_float2(0.f, 0.f);
        #pragma unroll
        for (int hh = 0; hh < 2; hh++){
            int r = 2*rp + hh;
            int nd = nodes[r];
            float sv = 0.5f * (hh ? u.y : u.x);
            float o  = sv * (c0 + c1*sv + c2*sv*sv);
            if (HAS_SC) o += (hh ? v.y : v.x);
            ov[r] = o;
            if (!HAS_SC && nd >= 0){
                g_scal[nd*FD + tid] = o;
                g_agg[nd*FD + tid]  = 0.0f;     // prep for layer 1
            }
        }
    }

    // ---- fused readout ----
    if (!HAS_SC){
        float w0 = roA[tid];
        __syncthreads();
        #pragma unroll
        for (int r = 0; r < 16; r++) Wl[r*FD + tid] = ov[r]*w0;
        __syncthreads();
        int w = tid >> 5, lane = tid & 31;
        #pragma unroll
        for (int q = 0; q < 4; q++){
            int r = w*4 + q;
            float v = Wl[r*FD+lane] + Wl[r*FD+lane+32]
                    + Wl[r*FD+lane+64] + Wl[r*FD+lane+96];
            #pragma unroll
            for (int o2 = 16; o2; o2 >>= 1) v += __shfl_xor_sync(0xffffffffu, v, o2);
            if (lane == 0 && nodes[r] >= 0) out[nodes[r]*2] = v;
        }
    } else {
        __syncthreads();
        for (int i = tid; i < FD*16; i += 128) Ws[i] = roA[i];   // W1 [f][16]
        #pragma unroll
        for (int r = 0; r < 16; r++) Wl[r*FD + tid] = ov[r];
        __syncthreads();
        int rr = tid >> 3, jj = tid & 7;
        float p0 = 0.0f, p1 = 0.0f;
        #pragma unroll 4
        for (int f = 0; f < FD; f++){
            float sv = Wl[rr*FD + f];
            p0 = fmaf(sv, Ws[f*16 + jj],     p0);
            p1 = fmaf(sv, Ws[f*16 + jj + 8], p1);
        }
        float h0 = __fdividef(p0, 1.0f + __expf(-p0));
        float h1 = __fdividef(p1, 1.0f + __expf(-p1));
        float v = h0*roB[jj] + h1*roB[jj + 8];
        v += __shfl_xor_sync(0xffffffffu, v, 1);
        v += __shfl_xor_sync(0xffffffffu, v, 2);
        v += __shfl_xor_sync(0xffffffffu, v, 4);
        if (jj == 0 && nodes[rr] >= 0) out[nodes[rr]*2 + 1] = v;

        // restore invariant: cnt/cur zero for the next kernel_launch invocation
        if (blockIdx.x == 0 && tid < NSPEC){ g_cnt[tid] = 0; g_cur[tid] = 0; }
    }
}

// ---------------- launcher ---------------------------------------------------
extern "C" void kernel_launch(void* const* d_in, const int* in_sizes, int n_in,
                              void* d_out, int out_size)
{
    const float* vectors = (const float*)d_in[0];
    const int*   spec    = (const int*)  d_in[1];
    const int*   snd     = (const int*)  d_in[2];
    const int*   rcv     = (const int*)  d_in[3];
    const float* emb     = (const float*)d_in[4];
    const float* rW1     = (const float*)d_in[5];
    const float* rb1     = (const float*)d_in[6];
    const float* rW2     = (const float*)d_in[7];
    const float* linW    = (const float*)d_in[8];
    const float* pc      = (const float*)d_in[9];
    const float* scW     = (const float*)d_in[10];
    const float* ro0     = (const float*)d_in[11];
    const float* ro1W1   = (const float*)d_in[12];
    const float* ro1W2   = (const float*)d_in[13];
    float* out = (float*)d_out;

    const int LAYER_LIN  = NSPEC * 4 * FD * FD;
    const int LAYER_PC   = NSPEC * 3 * FD;

    float* w2t_ptr;  cudaGetSymbolAddress((void**)&w2t_ptr, g_w2t);

    int nchunks = NN/16 + NSPEC;

    k_prep<<<1939, 256>>>(vectors, rW2, spec, emb);                  // 1 (+counts)
    k_b24<<<(NN + 255)/256, 256>>>(spec);                            // 2
    k_edge<<<GRIDE2, 256>>>(rW1, rb1, w2t_ptr, snd, rcv);            // 3  layer 0
    k_node<false><<<nchunks, 128>>>(linW, linW, pc, ro0, ro0, out);  // 4 (+ro0)
    k_edge<<<GRIDE2, 256>>>(rW1 + NBASIS*NHID, rb1 + NHID,
                            w2t_ptr + NHID*FD, snd, rcv);            // 5  layer 1
    k_node<true><<<nchunks, 128>>>(linW + LAYER_LIN, scW + LAYER_LIN,
                                   pc + LAYER_PC, ro1W1, ro1W2, out);// 6 (+ro1, +cnt reset)
}